// round 1
// baseline (speedup 1.0000x reference)
#include <cuda_runtime.h>
#include <cstdint>

// Problem constants (fixed by the reference setup)
#define NNODES 8192
#define FEAT   128
#define CAP    128   // max nnz/row we store; Poisson(33) => P(row>128) ~ 0

// ---------------- device scratch (no allocations allowed) ----------------
__device__ int   g_nnz[NNODES];
__device__ int   g_col[NNODES * CAP];
__device__ float g_z1[NNODES * FEAT];
__device__ float g_z2[NNODES * FEAT];
__device__ float g_z3[NNODES * FEAT];
__device__ float g_u0[NNODES * FEAT];
__device__ float g_u1[NNODES * FEAT];

// ---------------- 1) CSR build: one warp per row, deterministic order ----
__global__ void ib_csr_build(const float* __restrict__ A) {
    int warp = (blockIdx.x * blockDim.x + threadIdx.x) >> 5;
    int lane = threadIdx.x & 31;
    if (warp >= NNODES) return;

    const float4* row = reinterpret_cast<const float4*>(A + (size_t)warp * NNODES);
    int* cols = g_col + warp * CAP;
    int base = 0;

    // 8192 cols / (2 * 128 per pair) = 32 outer iterations, MLP=2 per warp
    for (int c4 = 0; c4 < NNODES / 4; c4 += 64) {
        float4 v0 = row[c4 + lane];
        float4 v1 = row[c4 + 32 + lane];
        #pragma unroll
        for (int half = 0; half < 2; half++) {
            float4 v  = half ? v1 : v0;
            int cbase = (c4 + half * 32 + lane) * 4;
            float vals[4] = {v.x, v.y, v.z, v.w};
            #pragma unroll
            for (int k = 0; k < 4; k++) {
                unsigned m = __ballot_sync(0xffffffffu, vals[k] != 0.0f);
                if (vals[k] != 0.0f) {
                    int off = base + __popc(m & ((1u << lane) - 1u));
                    if (off < CAP) cols[off] = cbase + k;
                }
                base += __popc(m);
            }
        }
    }
    if (lane == 0) g_nnz[warp] = base < CAP ? base : CAP;
}

// ---------------- 2) small GEMM: z = x @ W  (64x128 tile, K-tiled) -------
// grid = (NNODES/64, 1, 3); block = 256 threads (16 col-groups x 16 row-groups)
__global__ void ib_gemm_xw(const float* __restrict__ x,
                           const float* __restrict__ W1,
                           const float* __restrict__ W2,
                           const float* __restrict__ W3) {
    __shared__ __align__(16) float xs[64][33];   // padded
    __shared__ __align__(16) float Ws[32][128];

    const float* W = (blockIdx.z == 0) ? W1 : (blockIdx.z == 1) ? W2 : W3;
    float* z       = (blockIdx.z == 0) ? g_z1 : (blockIdx.z == 1) ? g_z2 : g_z3;

    int tid = threadIdx.x;
    int tx = tid & 15;        // col group: cols tx*8 .. tx*8+7
    int ty = tid >> 4;        // row group: rows ty*4 .. ty*4+3
    int r0 = blockIdx.x * 64;

    float acc[4][8];
    #pragma unroll
    for (int i = 0; i < 4; i++)
        #pragma unroll
        for (int j = 0; j < 8; j++) acc[i][j] = 0.0f;

    for (int kt = 0; kt < FEAT; kt += 32) {
        // load x tile [64][32]
        for (int idx = tid; idx < 64 * 32; idx += 256) {
            int rr = idx >> 5, kk = idx & 31;
            xs[rr][kk] = x[(size_t)(r0 + rr) * FEAT + kt + kk];
        }
        // load W tile [32][128]
        for (int idx = tid; idx < 32 * 128; idx += 256) {
            int kk = idx >> 7, cc = idx & 127;
            Ws[kk][cc] = W[(size_t)(kt + kk) * FEAT + cc];
        }
        __syncthreads();

        #pragma unroll
        for (int k = 0; k < 32; k++) {
            float4 b0 = *reinterpret_cast<const float4*>(&Ws[k][tx * 8]);
            float4 b1 = *reinterpret_cast<const float4*>(&Ws[k][tx * 8 + 4]);
            float bb[8] = {b0.x, b0.y, b0.z, b0.w, b1.x, b1.y, b1.z, b1.w};
            #pragma unroll
            for (int i = 0; i < 4; i++) {
                float a = xs[ty * 4 + i][k];
                #pragma unroll
                for (int j = 0; j < 8; j++) acc[i][j] = fmaf(a, bb[j], acc[i][j]);
            }
        }
        __syncthreads();
    }

    #pragma unroll
    for (int i = 0; i < 4; i++) {
        float* dst = z + (size_t)(r0 + ty * 4 + i) * FEAT + tx * 8;
        *reinterpret_cast<float4*>(dst)     = make_float4(acc[i][0], acc[i][1], acc[i][2], acc[i][3]);
        *reinterpret_cast<float4*>(dst + 4) = make_float4(acc[i][4], acc[i][5], acc[i][6], acc[i][7]);
    }
}

// ---------------- 3) SpMM pass: out[r] = scale * (add[r] + sum_j yin[col_j]) ----
// grid = NNODES blocks, 128 threads (one per feature)
__global__ void ib_spmm(float* __restrict__ out,
                        const float* __restrict__ yin,
                        const float* __restrict__ addv,
                        float scale) {
    __shared__ int s_cols[CAP];
    int row = blockIdx.x;
    int tid = threadIdx.x;

    int nnz = g_nnz[row];
    if (tid < nnz) s_cols[tid] = g_col[row * CAP + tid];
    __syncthreads();

    float acc = addv ? addv[(size_t)row * FEAT + tid] : 0.0f;

    int i = 0;
    for (; i + 4 <= nnz; i += 4) {
        int c0 = s_cols[i], c1 = s_cols[i + 1], c2 = s_cols[i + 2], c3 = s_cols[i + 3];
        float a = yin[(size_t)c0 * FEAT + tid];
        float b = yin[(size_t)c1 * FEAT + tid];
        float c = yin[(size_t)c2 * FEAT + tid];
        float d = yin[(size_t)c3 * FEAT + tid];
        acc += (a + b) + (c + d);
    }
    for (; i < nnz; i++) acc += yin[(size_t)s_cols[i] * FEAT + tid];

    out[(size_t)row * FEAT + tid] = acc * scale;
}

// ---------------- launch ----------------
extern "C" void kernel_launch(void* const* d_in, const int* in_sizes, int n_in,
                              void* d_out, int out_size) {
    const float* x  = (const float*)d_in[0];
    const float* A  = (const float*)d_in[1];
    const float* W1 = (const float*)d_in[2];
    const float* W2 = (const float*)d_in[3];
    const float* W3 = (const float*)d_in[4];
    float* out = (float*)d_out;

    // resolve device-global scratch addresses (host-side symbols work directly
    // in <<<>>> since they're __device__ arrays referenced inside kernels)
    ib_csr_build<<<NNODES / 8, 256>>>(A);               // 8 warps/block
    ib_gemm_xw<<<dim3(NNODES / 64, 1, 3), 256>>>(x, W1, W2, W3);

    // Horner: out = (A(z1 + A(z2 + A z3))) / 3
    float* z1; float* z2; float* z3; float* u0; float* u1;
    // device symbols are directly usable as pointers inside kernels; here we
    // pass them via kernel args using the symbols' device addresses:
    // (taking address of __device__ var in host code yields the device address
    //  only via cudaGetSymbolAddress; instead just reference the arrays in a
    //  tiny wrapper — simplest: use the fact that we can pass them from device
    //  code. To stay allocation-free and capture-safe, use cudaGetSymbolAddress
    //  which is not a memory allocation.)
    cudaGetSymbolAddress((void**)&z1, g_z1);
    cudaGetSymbolAddress((void**)&z2, g_z2);
    cudaGetSymbolAddress((void**)&z3, g_z3);
    cudaGetSymbolAddress((void**)&u0, g_u0);
    cudaGetSymbolAddress((void**)&u1, g_u1);

    ib_spmm<<<NNODES, FEAT>>>(u0, z3, z2, 1.0f);        // u0 = z2 + A z3
    ib_spmm<<<NNODES, FEAT>>>(u1, u0, z1, 1.0f);        // u1 = z1 + A u0
    ib_spmm<<<NNODES, FEAT>>>(out, u1, nullptr, 1.0f / 3.0f);
}

// round 2
// speedup vs baseline: 1.3099x; 1.3099x over previous
#include <cuda_runtime.h>
#include <cstdint>

#define NNODES 8192
#define FEAT   128
#define CAP    128            // max nnz/row stored; Binomial(8192,0.004) -> P(>128) ~ 0

#define GEMM_BLOCKS 384       // 3 branches x 128 row-tiles
#define CSR_BLOCKS  1024      // 8 rows (warps) per block

// ---------------- device scratch (no allocations allowed) ----------------
__device__ __align__(16) int   g_nnz[NNODES];
__device__ __align__(16) int   g_col[NNODES * CAP];
__device__ __align__(16) float g_z1[NNODES * FEAT];
__device__ __align__(16) float g_z2[NNODES * FEAT];
__device__ __align__(16) float g_z3[NNODES * FEAT];
__device__ __align__(16) float g_u0[NNODES * FEAT];
__device__ __align__(16) float g_u1[NNODES * FEAT];

// =====================================================================
// K1: heterogeneous kernel.
//   blocks [0, GEMM_BLOCKS)              : z_k = x @ W_k   (FMA-bound)
//   blocks [GEMM_BLOCKS, +CSR_BLOCKS)    : CSR build of A  (HBM-bound)
// GEMM blocks are scheduled first so they overlap the 256MB A stream.
// =====================================================================
__global__ void __launch_bounds__(256, 4)
ib_build(const float* __restrict__ A,
         const float* __restrict__ x,
         const float* __restrict__ W1,
         const float* __restrict__ W2,
         const float* __restrict__ W3) {

    if (blockIdx.x < GEMM_BLOCKS) {
        // ---------------- GEMM branch: 64x128 tile, K-tiled by 32 ----------
        __shared__ __align__(16) float xs[64][33];
        __shared__ __align__(16) float Ws[32][128];

        int bz = blockIdx.x >> 7;          // 0..2  (branch)
        int bx = blockIdx.x & 127;         // row tile
        const float* W = (bz == 0) ? W1 : (bz == 1) ? W2 : W3;
        float* z       = (bz == 0) ? g_z1 : (bz == 1) ? g_z2 : g_z3;

        int tid = threadIdx.x;
        int tx = tid & 15;                  // cols tx*8 .. +7
        int ty = tid >> 4;                  // rows ty*4 .. +3
        int r0 = bx * 64;

        float acc[4][8];
        #pragma unroll
        for (int i = 0; i < 4; i++)
            #pragma unroll
            for (int j = 0; j < 8; j++) acc[i][j] = 0.0f;

        for (int kt = 0; kt < FEAT; kt += 32) {
            for (int idx = tid; idx < 64 * 32; idx += 256) {
                int rr = idx >> 5, kk = idx & 31;
                xs[rr][kk] = x[(size_t)(r0 + rr) * FEAT + kt + kk];
            }
            for (int idx = tid; idx < 32 * 128; idx += 256) {
                int kk = idx >> 7, cc = idx & 127;
                Ws[kk][cc] = W[(size_t)(kt + kk) * FEAT + cc];
            }
            __syncthreads();

            #pragma unroll
            for (int k = 0; k < 32; k++) {
                float4 b0 = *reinterpret_cast<const float4*>(&Ws[k][tx * 8]);
                float4 b1 = *reinterpret_cast<const float4*>(&Ws[k][tx * 8 + 4]);
                float bb[8] = {b0.x, b0.y, b0.z, b0.w, b1.x, b1.y, b1.z, b1.w};
                #pragma unroll
                for (int i = 0; i < 4; i++) {
                    float a = xs[ty * 4 + i][k];
                    #pragma unroll
                    for (int j = 0; j < 8; j++) acc[i][j] = fmaf(a, bb[j], acc[i][j]);
                }
            }
            __syncthreads();
        }

        #pragma unroll
        for (int i = 0; i < 4; i++) {
            float* dst = z + (size_t)(r0 + ty * 4 + i) * FEAT + tx * 8;
            *reinterpret_cast<float4*>(dst)     = make_float4(acc[i][0], acc[i][1], acc[i][2], acc[i][3]);
            *reinterpret_cast<float4*>(dst + 4) = make_float4(acc[i][4], acc[i][5], acc[i][6], acc[i][7]);
        }
        return;
    }

    // ---------------- CSR branch: warp-per-row, sorted column output --------
    {
        int row  = (blockIdx.x - GEMM_BLOCKS) * 8 + (threadIdx.x >> 5);
        int lane = threadIdx.x & 31;

        const float4* r4 = reinterpret_cast<const float4*>(A + (size_t)row * NNODES);
        int* cols = g_col + row * CAP;
        int base = 0;

        // lane owns 16 CONTIGUOUS columns per iter: cols it*512 + lane*16 .. +15
        // (4 float4 at indices it*128 + lane*4 + j)
        float4 buf[4];
        #pragma unroll
        for (int j = 0; j < 4; j++) buf[j] = r4[lane * 4 + j];

        #pragma unroll 1
        for (int it = 0; it < 16; it++) {
            // prefetch next tile (wraps to 0 on last iter; harmless redundant load)
            int nit = (it + 1) & 15;
            float4 nxt[4];
            #pragma unroll
            for (int j = 0; j < 4; j++) nxt[j] = r4[nit * 128 + lane * 4 + j];

            unsigned m = 0;
            #pragma unroll
            for (int j = 0; j < 4; j++) {
                m |= (unsigned)(buf[j].x != 0.0f) << (j * 4 + 0);
                m |= (unsigned)(buf[j].y != 0.0f) << (j * 4 + 1);
                m |= (unsigned)(buf[j].z != 0.0f) << (j * 4 + 2);
                m |= (unsigned)(buf[j].w != 0.0f) << (j * 4 + 3);
            }
            int cnt  = __popc(m);
            int incl = cnt;
            #pragma unroll
            for (int d = 1; d < 32; d <<= 1) {
                int t = __shfl_up_sync(0xffffffffu, incl, d);
                if (lane >= d) incl += t;
            }
            int myoff   = base + incl - cnt;
            int total   = __shfl_sync(0xffffffffu, incl, 31);
            int colbase = it * 512 + lane * 16;

            while (m) {
                int k = __ffs(m) - 1;
                m &= m - 1;
                if (myoff < CAP) cols[myoff] = colbase + k;
                myoff++;
            }
            base += total;

            #pragma unroll
            for (int j = 0; j < 4; j++) buf[j] = nxt[j];
        }
        if (lane == 31) g_nnz[row] = base < CAP ? base : CAP;
    }
}

// =====================================================================
// K2: SpMM pass, warp-per-row with float4 gathers.
//   out[r] = scale * (add[r] + sum_j yin[col_j])
// grid = NNODES/8 blocks, 256 threads (8 warps = 8 rows)
// =====================================================================
__global__ void __launch_bounds__(256, 8)
ib_spmm(float4* __restrict__ out,
        const float4* __restrict__ yin,
        const float4* __restrict__ addv,
        float scale) {
    __shared__ int s_cols[8][CAP];

    int wid  = threadIdx.x >> 5;
    int lane = threadIdx.x & 31;
    int row  = blockIdx.x * 8 + wid;

    int nnz = g_nnz[row];
    const int* cp = g_col + row * CAP;
    int* sc = s_cols[wid];
    for (int j = lane; j < nnz; j += 32) sc[j] = cp[j];
    __syncwarp();

    float4 acc = addv ? addv[(size_t)row * 32 + lane]
                      : make_float4(0.f, 0.f, 0.f, 0.f);

    int i = 0;
    for (; i + 8 <= nnz; i += 8) {
        float4 v[8];
        #pragma unroll
        for (int j = 0; j < 8; j++) {
            int c = sc[i + j];                      // LDS broadcast, no conflict
            v[j] = yin[(size_t)c * 32 + lane];      // 128b coalesced gather
        }
        #pragma unroll
        for (int j = 0; j < 8; j++) {
            acc.x += v[j].x; acc.y += v[j].y; acc.z += v[j].z; acc.w += v[j].w;
        }
    }
    for (; i < nnz; i++) {
        int c = sc[i];
        float4 v = yin[(size_t)c * 32 + lane];
        acc.x += v.x; acc.y += v.y; acc.z += v.z; acc.w += v.w;
    }

    acc.x *= scale; acc.y *= scale; acc.z *= scale; acc.w *= scale;
    out[(size_t)row * 32 + lane] = acc;
}

// ---------------- launch ----------------
extern "C" void kernel_launch(void* const* d_in, const int* in_sizes, int n_in,
                              void* d_out, int out_size) {
    const float* x  = (const float*)d_in[0];
    const float* A  = (const float*)d_in[1];
    const float* W1 = (const float*)d_in[2];
    const float* W2 = (const float*)d_in[3];
    const float* W3 = (const float*)d_in[4];
    float4* out = (float4*)d_out;

    float4 *z1, *z2, *z3, *u0, *u1;
    cudaGetSymbolAddress((void**)&z1, g_z1);
    cudaGetSymbolAddress((void**)&z2, g_z2);
    cudaGetSymbolAddress((void**)&z3, g_z3);
    cudaGetSymbolAddress((void**)&u0, g_u0);
    cudaGetSymbolAddress((void**)&u1, g_u1);

    // K1: GEMM (z1,z2,z3) + CSR build, overlapped in one grid
    ib_build<<<GEMM_BLOCKS + CSR_BLOCKS, 256>>>(A, x, W1, W2, W3);

    // Horner: out = A*(z1 + A*(z2 + A*z3)) / 3
    ib_spmm<<<NNODES / 8, 256>>>(u0, z3, z2, 1.0f);          // u0 = z2 + A z3
    ib_spmm<<<NNODES / 8, 256>>>(u1, u0, z1, 1.0f);          // u1 = z1 + A u0
    ib_spmm<<<NNODES / 8, 256>>>(out, u1, nullptr, 1.0f / 3.0f);
}